// round 1
// baseline (speedup 1.0000x reference)
#include <cuda_runtime.h>

// Problem constants (fixed by the reference).
#define TT   1024
#define BB   16384
#define CH   64          // steps per chunk
#define NCH  (TT / CH)   // 16 chunks
#define HB   (BB / 2)    // batch pairs

typedef unsigned long long u64;

static_assert(CH == 64, "kB squaring count assumes CH=64");
static_assert(TT % CH == 0, "");

// Scratch: db partials (zero-state per chunk) and checkpoints (true db at chunk entry).
// Planar layout [chunk][dim][batch] for coalesced access.
__device__ float g_part[NCH * 6 * BB];
__device__ float g_ckpt[NCH * 6 * BB];

// ---- f32x2 helpers (sm_100+ packed fp32 pipe) ----
__device__ __forceinline__ u64 pack2(float lo, float hi) {
    u64 r; asm("mov.b64 %0,{%1,%2};" : "=l"(r) : "f"(lo), "f"(hi)); return r;
}
__device__ __forceinline__ void unpack2(u64 v, float& lo, float& hi) {
    asm("mov.b64 {%0,%1},%2;" : "=f"(lo), "=f"(hi) : "l"(v));
}
__device__ __forceinline__ u64 fma2(u64 a, u64 b, u64 c) {
    u64 d; asm("fma.rn.f32x2 %0,%1,%2,%3;" : "=l"(d) : "l"(a), "l"(b), "l"(c)); return d;
}
__device__ __forceinline__ u64 mul2(u64 a, u64 b) {
    u64 d; asm("mul.rn.f32x2 %0,%1,%2;" : "=l"(d) : "l"(a), "l"(b)); return d;
}
__device__ __forceinline__ float ex2f(float x) {
    float y; asm("ex2.approx.f32 %0,%1;" : "=f"(y) : "f"(x)); return y;
}
__device__ __forceinline__ float rcpf(float x) {
    float y; asm("rcp.approx.f32 %0,%1;" : "=f"(y) : "f"(x)); return y;
}

// ============================================================
// Kernel A: per-chunk zero-state db partials.
// grid (BB/256, NCH), block 256. One thread = one batch element of one chunk.
// ============================================================
__global__ void __launch_bounds__(256) kA(const float* __restrict__ targets,
                                          const float* __restrict__ Wx,
                                          const float* __restrict__ Wu) {
    int b = blockIdx.x * 256 + threadIdx.x;
    int c = blockIdx.y;

    float wx[36], wu[6];
#pragma unroll
    for (int i = 0; i < 36; i++) wx[i] = __ldg(Wx + i);
#pragma unroll
    for (int i = 0; i < 6; i++) wu[i] = __ldg(Wu + i);

    float db[6] = {0.f, 0.f, 0.f, 0.f, 0.f, 0.f};
    int t0 = c * CH;
#pragma unroll 4
    for (int s = 0; s < CH; s++) {
        int t = t0 + s;
        float u = 0.f;
        if (t > 0) u = targets[(size_t)(t - 1) * BB + b];
        float nd[6];
#pragma unroll
        for (int i = 0; i < 6; i++) {
            float a = wu[i] * u;
#pragma unroll
            for (int j = 0; j < 6; j++) a = fmaf(wx[i * 6 + j], db[j], a);
            nd[i] = a;
        }
#pragma unroll
        for (int i = 0; i < 6; i++) db[i] = nd[i];
    }
#pragma unroll
    for (int i = 0; i < 6; i++)
        g_part[((size_t)c * 6 + i) * BB + b] = db[i];
}

// ============================================================
// Kernel B: scan across chunks. ckpt[c] = true db entering chunk c.
// db_in(c+1) = Wx^CH * db_in(c) + partial(c).  Wx^64 computed by 6 squarings.
// grid (BB/256), block 256.
// ============================================================
__global__ void __launch_bounds__(256) kB(const float* __restrict__ Wx) {
    int b = blockIdx.x * 256 + threadIdx.x;

    float M[36], Tm[36];
#pragma unroll
    for (int i = 0; i < 36; i++) M[i] = __ldg(Wx + i);

#pragma unroll 1
    for (int p = 0; p < 6; p++) {  // M <- M*M, six times: Wx^64
#pragma unroll
        for (int i = 0; i < 6; i++)
#pragma unroll
            for (int j = 0; j < 6; j++) {
                float a = 0.f;
#pragma unroll
                for (int k = 0; k < 6; k++) a = fmaf(M[i * 6 + k], M[k * 6 + j], a);
                Tm[i * 6 + j] = a;
            }
#pragma unroll
        for (int i = 0; i < 36; i++) M[i] = Tm[i];
    }

    float v[6] = {0.f, 0.f, 0.f, 0.f, 0.f, 0.f};
#pragma unroll 1
    for (int c = 0; c < NCH; c++) {
#pragma unroll
        for (int i = 0; i < 6; i++)
            g_ckpt[((size_t)c * 6 + i) * BB + b] = v[i];
        float pr[6];
#pragma unroll
        for (int i = 0; i < 6; i++)
            pr[i] = g_part[((size_t)c * 6 + i) * BB + b];
        float nv[6];
#pragma unroll
        for (int i = 0; i < 6; i++) {
            float a = pr[i];
#pragma unroll
            for (int j = 0; j < 6; j++) a = fmaf(M[i * 6 + j], v[j], a);
            nv[i] = a;
        }
#pragma unroll
        for (int i = 0; i < 6; i++) v[i] = nv[i];
    }
}

// ============================================================
// Kernel C: main fused kernel. One thread = one pair of batch elements
// (b, b+HB) packed into f32x2 lanes, for one chunk of 64 steps.
// Weights live in SMEM pre-duplicated as f32x2 pairs, read via LDS.128.
// grid (HB/128, NCH), block 128.
// SMEM layout (u64 units):
//   rows i=0..5 at i*8:        [Wx i0..i5, Wu i, pad]
//   rows j=0..19 at 48+j*16:   [W1 j0..j11, b1 j, -2*W2 j, pad, pad]
//   [368]:                     oinit = b2 + sum_j W2[j]   (packed)
// ============================================================
#define SW_ROWJ(j) (48 + (j) * 16)
__global__ void __launch_bounds__(128) kC(const float* __restrict__ inputs,
                                          const float* __restrict__ targets,
                                          const float* __restrict__ Wx,
                                          const float* __restrict__ Wu,
                                          const float* __restrict__ W1,
                                          const float* __restrict__ b1,
                                          const float* __restrict__ W2,
                                          const float* __restrict__ b2,
                                          float* __restrict__ out) {
    __shared__ __align__(16) u64 sw[372];
    int tid = threadIdx.x;

    if (tid < 36) {
        float w = __ldg(Wx + tid);
        sw[(tid / 6) * 8 + (tid % 6)] = pack2(w, w);
    } else if (tid < 42) {
        int i = tid - 36;
        float w = __ldg(Wu + i);
        sw[i * 8 + 6] = pack2(w, w);
        sw[i * 8 + 7] = 0ull;
    } else if (tid < 62) {
        int j = tid - 42;
        for (int i = 0; i < 12; i++) {
            float w = __ldg(W1 + j * 12 + i);
            sw[SW_ROWJ(j) + i] = pack2(w, w);
        }
        float bj = __ldg(b1 + j);
        sw[SW_ROWJ(j) + 12] = pack2(bj, bj);
        float w2j = __ldg(W2 + j);
        sw[SW_ROWJ(j) + 13] = pack2(-2.f * w2j, -2.f * w2j);
        sw[SW_ROWJ(j) + 14] = 0ull;
        sw[SW_ROWJ(j) + 15] = 0ull;
    } else if (tid == 62) {
        float s = __ldg(b2);
        for (int j = 0; j < 20; j++) s += __ldg(W2 + j);
        sw[368] = pack2(s, s);
    }
    __syncthreads();

    int c  = blockIdx.y;
    int p  = blockIdx.x * 128 + tid;   // 0..HB-1
    int b0 = p;
    int b1i = p + HB;

    u64 db[6];
#pragma unroll
    for (int i = 0; i < 6; i++)
        db[i] = pack2(g_ckpt[((size_t)c * 6 + i) * BB + b0],
                      g_ckpt[((size_t)c * 6 + i) * BB + b1i]);

    const u64 oinit = sw[368];
    const u64 kk = pack2(2.8853900817779268f, 2.8853900817779268f);  // 2*log2(e)
    const float2* xin = reinterpret_cast<const float2*>(inputs);

#pragma unroll 1
    for (int s = 0; s < CH; s++) {
        int t = c * CH + s;

        // --- inputs x for both elements (6 floats each, 8B-aligned) ---
        size_t base0 = ((size_t)t * BB + b0) * 3;   // float2 units
        size_t base1 = ((size_t)t * BB + b1i) * 3;
        float2 xa0 = xin[base0], xb0 = xin[base0 + 1], xc0 = xin[base0 + 2];
        float2 xa1 = xin[base1], xb1 = xin[base1 + 1], xc1 = xin[base1 + 2];
        u64 xr[6];
        xr[0] = pack2(xa0.x, xa1.x);
        xr[1] = pack2(xa0.y, xa1.y);
        xr[2] = pack2(xb0.x, xb1.x);
        xr[3] = pack2(xb0.y, xb1.y);
        xr[4] = pack2(xc0.x, xc1.x);
        xr[5] = pack2(xc0.y, xc1.y);

        // --- teacher-forced feedback u = targets[t-1] (0 at t=0) ---
        float u0 = 0.f, u1v = 0.f;
        if (t > 0) {
            u0  = targets[(size_t)(t - 1) * BB + b0];
            u1v = targets[(size_t)(t - 1) * BB + b1i];
        }
        u64 uu = pack2(u0, u1v);

        // --- delay buffer update: db = Wx*db + Wu*u ---
        u64 nd[6];
#pragma unroll
        for (int i = 0; i < 6; i++) {
            const ulonglong2* r = reinterpret_cast<const ulonglong2*>(&sw[i * 8]);
            ulonglong2 q0 = r[0], q1 = r[1], q2 = r[2], q3 = r[3];
            u64 a = mul2(q3.x, uu);
            a = fma2(q0.x, db[0], a);
            a = fma2(q0.y, db[1], a);
            a = fma2(q1.x, db[2], a);
            a = fma2(q1.y, db[3], a);
            a = fma2(q2.x, db[4], a);
            a = fma2(q2.y, db[5], a);
            nd[i] = a;
        }
#pragma unroll
        for (int i = 0; i < 6; i++) db[i] = nd[i];

        // --- MLP: out = b2 + sum_j W2_j * tanh(W1_j . [db,x] + b1_j)
        //     tanh(a) = 1 - 2*rcp(1 + exp2(a*2log2e)); the 1's and -2*W2 are folded.
        u64 oacc = oinit;
#pragma unroll
        for (int j = 0; j < 20; j++) {
            const ulonglong2* r = reinterpret_cast<const ulonglong2*>(&sw[SW_ROWJ(j)]);
            ulonglong2 q0 = r[0], q1 = r[1], q2 = r[2], q3 = r[3], q4 = r[4], q5 = r[5], q6 = r[6];
            u64 acc = q6.x;  // b1_j
            acc = fma2(q0.x, db[0], acc);
            acc = fma2(q0.y, db[1], acc);
            acc = fma2(q1.x, db[2], acc);
            acc = fma2(q1.y, db[3], acc);
            acc = fma2(q2.x, db[4], acc);
            acc = fma2(q2.y, db[5], acc);
            acc = fma2(q3.x, xr[0], acc);
            acc = fma2(q3.y, xr[1], acc);
            acc = fma2(q4.x, xr[2], acc);
            acc = fma2(q4.y, xr[3], acc);
            acc = fma2(q5.x, xr[4], acc);
            acc = fma2(q5.y, xr[5], acc);
            u64 sc = mul2(acc, kk);
            float s0, s1;
            unpack2(sc, s0, s1);
            float e0 = ex2f(s0), e1 = ex2f(s1);
            float r0 = rcpf(e0 + 1.0f), r1 = rcpf(e1 + 1.0f);
            oacc = fma2(q6.y, pack2(r0, r1), oacc);  // q6.y = -2*W2_j
        }

        float o0, o1;
        unpack2(oacc, o0, o1);
        out[(size_t)t * BB + b0]  = o0;
        out[(size_t)t * BB + b1i] = o1;
    }
}

// ============================================================
extern "C" void kernel_launch(void* const* d_in, const int* in_sizes, int n_in,
                              void* d_out, int out_size) {
    (void)in_sizes; (void)n_in; (void)out_size;
    const float* inputs  = (const float*)d_in[0];
    const float* targets = (const float*)d_in[1];
    const float* Wx      = (const float*)d_in[2];
    const float* Wu      = (const float*)d_in[3];
    const float* W1      = (const float*)d_in[4];
    const float* b1      = (const float*)d_in[5];
    const float* W2      = (const float*)d_in[6];
    const float* b2      = (const float*)d_in[7];
    float* out = (float*)d_out;

    dim3 gA(BB / 256, NCH);
    kA<<<gA, 256>>>(targets, Wx, Wu);
    kB<<<BB / 256, 256>>>(Wx);
    dim3 gC(HB / 128, NCH);
    kC<<<gC, 128>>>(inputs, targets, Wx, Wu, W1, b1, W2, b2, out);
}

// round 2
// speedup vs baseline: 1.1218x; 1.1218x over previous
#include <cuda_runtime.h>

// Problem constants (fixed by the reference).
#define TT   1024
#define BB   16384
#define CH   64          // steps per chunk
#define NCH  (TT / CH)   // 16 chunks
#define HB   (BB / 2)    // batch pairs

typedef unsigned long long u64;

static_assert(CH == 64, "power-table size assumes CH=64");
static_assert(TT % CH == 0, "");

// Scratch.
__device__ float g_part[NCH * 6 * BB];   // zero-state per-chunk db partials, [chunk][dim][batch]
__device__ float g_ckpt[NCH * 6 * BB];   // true db at chunk entry
__device__ float g_m[CH * 6];            // m_s = Wx^s * Wu
__device__ float g_M64[36];              // Wx^64

// ---- f32x2 helpers (sm_100+ packed fp32 pipe) ----
__device__ __forceinline__ u64 pack2(float lo, float hi) {
    u64 r; asm("mov.b64 %0,{%1,%2};" : "=l"(r) : "f"(lo), "f"(hi)); return r;
}
__device__ __forceinline__ void unpack2(u64 v, float& lo, float& hi) {
    asm("mov.b64 {%0,%1},%2;" : "=f"(lo), "=f"(hi) : "l"(v));
}
__device__ __forceinline__ u64 fma2(u64 a, u64 b, u64 c) {
    u64 d; asm("fma.rn.f32x2 %0,%1,%2,%3;" : "=l"(d) : "l"(a), "l"(b), "l"(c)); return d;
}
__device__ __forceinline__ u64 mul2(u64 a, u64 b) {
    u64 d; asm("mul.rn.f32x2 %0,%1,%2;" : "=l"(d) : "l"(a), "l"(b)); return d;
}
__device__ __forceinline__ float tanh_(float x) {
    float y; asm("tanh.approx.f32 %0,%1;" : "=f"(y) : "f"(x)); return y;
}

// ============================================================
// Kernel P: tiny precompute. m_s = Wx^s Wu (s=0..63) and Wx^64.
// One block of 64 threads.
// ============================================================
__global__ void __launch_bounds__(64) kP(const float* __restrict__ Wx,
                                         const float* __restrict__ Wu) {
    __shared__ float sM[36], sm[6], sP[36], st[36];
    int t = threadIdx.x;
    if (t < 36) sM[t] = Wx[t];
    if (t < 6)  sm[t] = Wu[t];
    __syncthreads();

    // powers of Wx applied to Wu
    for (int s = 0; s < CH; s++) {
        if (t < 6) g_m[s * 6 + t] = sm[t];
        __syncthreads();
        float nv = 0.f;
        if (t < 6) {
#pragma unroll
            for (int k = 0; k < 6; k++) nv = fmaf(sM[t * 6 + k], sm[k], nv);
        }
        __syncthreads();
        if (t < 6) sm[t] = nv;
        __syncthreads();
    }

    // Wx^64 by 6 squarings
    if (t < 36) sP[t] = sM[t];
    __syncthreads();
    for (int p = 0; p < 6; p++) {
        if (t < 36) {
            int i = t / 6, j = t % 6;
            float a = 0.f;
#pragma unroll
            for (int k = 0; k < 6; k++) a = fmaf(sP[i * 6 + k], sP[k * 6 + j], a);
            st[t] = a;
        }
        __syncthreads();
        if (t < 36) sP[t] = st[t];
        __syncthreads();
    }
    if (t < 36) g_M64[t] = sP[t];
}

// ============================================================
// Kernel A: per-chunk zero-state db partials via convolution:
//   partial(c) = sum_s m_{63-s} * u_{t0+s},  u_t = targets[t-1] (0 at t=0).
// grid (BB/256, NCH), block 256.
// ============================================================
__global__ void __launch_bounds__(256) kA(const float* __restrict__ targets) {
    __shared__ float sm[CH * 6];
    int tid = threadIdx.x;
    for (int i = tid; i < CH * 6; i += 256) sm[i] = g_m[i];
    __syncthreads();

    int b = blockIdx.x * 256 + tid;
    int c = blockIdx.y;
    int t0 = c * CH;

    float acc[6] = {0.f, 0.f, 0.f, 0.f, 0.f, 0.f};
#pragma unroll 8
    for (int s = 0; s < CH; s++) {
        int t = t0 + s;
        float u = 0.f;
        if (t > 0) u = targets[(size_t)(t - 1) * BB + b];
        const float* mm = &sm[(CH - 1 - s) * 6];
#pragma unroll
        for (int i = 0; i < 6; i++) acc[i] = fmaf(mm[i], u, acc[i]);
    }
#pragma unroll
    for (int i = 0; i < 6; i++)
        g_part[((size_t)c * 6 + i) * BB + b] = acc[i];
}

// ============================================================
// Kernel B: scan across chunks. ckpt[c] = true db entering chunk c.
//   db_in(c+1) = Wx^64 * db_in(c) + partial(c).
// grid (BB/256), block 256.
// ============================================================
__global__ void __launch_bounds__(256) kB() {
    __shared__ float sM[36];
    int tid = threadIdx.x;
    if (tid < 36) sM[tid] = g_M64[tid];
    __syncthreads();

    int b = blockIdx.x * 256 + tid;
    float v[6] = {0.f, 0.f, 0.f, 0.f, 0.f, 0.f};
#pragma unroll 1
    for (int c = 0; c < NCH; c++) {
#pragma unroll
        for (int i = 0; i < 6; i++)
            g_ckpt[((size_t)c * 6 + i) * BB + b] = v[i];
        float pr[6];
#pragma unroll
        for (int i = 0; i < 6; i++)
            pr[i] = g_part[((size_t)c * 6 + i) * BB + b];
        float nv[6];
#pragma unroll
        for (int i = 0; i < 6; i++) {
            float a = pr[i];
#pragma unroll
            for (int j = 0; j < 6; j++) a = fmaf(sM[i * 6 + j], v[j], a);
            nv[i] = a;
        }
#pragma unroll
        for (int i = 0; i < 6; i++) v[i] = nv[i];
    }
}

// ============================================================
// Kernel C: main fused kernel. One thread = one pair of batch elements
// (b, b+HB) packed into f32x2 lanes, for one chunk of 64 steps.
// Weights in SMEM pre-duplicated as f32x2 pairs, read via LDS.128.
// grid (HB/128, NCH), block 128.
// SMEM layout (u64 units):
//   rows i=0..5 at i*8:        [Wx i0..i5, Wu i, pad]
//   rows j=0..19 at 48+j*16:   [W1 j0..j11, b1 j, W2 j, pad, pad]
// ============================================================
#define SW_ROWJ(j) (48 + (j) * 16)
__global__ void __launch_bounds__(128) kC(const float* __restrict__ inputs,
                                          const float* __restrict__ targets,
                                          const float* __restrict__ Wx,
                                          const float* __restrict__ Wu,
                                          const float* __restrict__ W1,
                                          const float* __restrict__ b1,
                                          const float* __restrict__ W2,
                                          const float* __restrict__ b2,
                                          float* __restrict__ out) {
    __shared__ __align__(16) u64 sw[368];
    int tid = threadIdx.x;

    if (tid < 36) {
        float w = __ldg(Wx + tid);
        sw[(tid / 6) * 8 + (tid % 6)] = pack2(w, w);
    } else if (tid < 42) {
        int i = tid - 36;
        float w = __ldg(Wu + i);
        sw[i * 8 + 6] = pack2(w, w);
        sw[i * 8 + 7] = 0ull;
    } else if (tid < 62) {
        int j = tid - 42;
        for (int i = 0; i < 12; i++) {
            float w = __ldg(W1 + j * 12 + i);
            sw[SW_ROWJ(j) + i] = pack2(w, w);
        }
        float bj = __ldg(b1 + j);
        sw[SW_ROWJ(j) + 12] = pack2(bj, bj);
        float w2j = __ldg(W2 + j);
        sw[SW_ROWJ(j) + 13] = pack2(w2j, w2j);
        sw[SW_ROWJ(j) + 14] = 0ull;
        sw[SW_ROWJ(j) + 15] = 0ull;
    }
    __syncthreads();

    int c   = blockIdx.y;
    int p   = blockIdx.x * 128 + tid;   // 0..HB-1
    int b0  = p;
    int b1i = p + HB;

    u64 db[6];
#pragma unroll
    for (int i = 0; i < 6; i++)
        db[i] = pack2(g_ckpt[((size_t)c * 6 + i) * BB + b0],
                      g_ckpt[((size_t)c * 6 + i) * BB + b1i]);

    float b2v = __ldg(b2);
    const u64 oinit = pack2(b2v, b2v);
    const float2* xin = reinterpret_cast<const float2*>(inputs);

#pragma unroll 1
    for (int s = 0; s < CH; s++) {
        int t = c * CH + s;

        // --- inputs x for both elements (6 floats each, 8B-aligned) ---
        size_t base0 = ((size_t)t * BB + b0) * 3;   // float2 units
        size_t base1 = ((size_t)t * BB + b1i) * 3;
        float2 xa0 = xin[base0], xb0 = xin[base0 + 1], xc0 = xin[base0 + 2];
        float2 xa1 = xin[base1], xb1 = xin[base1 + 1], xc1 = xin[base1 + 2];
        u64 xr[6];
        xr[0] = pack2(xa0.x, xa1.x);
        xr[1] = pack2(xa0.y, xa1.y);
        xr[2] = pack2(xb0.x, xb1.x);
        xr[3] = pack2(xb0.y, xb1.y);
        xr[4] = pack2(xc0.x, xc1.x);
        xr[5] = pack2(xc0.y, xc1.y);

        // --- teacher-forced feedback u = targets[t-1] (0 at t=0) ---
        float u0 = 0.f, u1v = 0.f;
        if (t > 0) {
            u0  = targets[(size_t)(t - 1) * BB + b0];
            u1v = targets[(size_t)(t - 1) * BB + b1i];
        }
        u64 uu = pack2(u0, u1v);

        // --- delay buffer update: db = Wx*db + Wu*u ---
        u64 nd[6];
#pragma unroll
        for (int i = 0; i < 6; i++) {
            const ulonglong2* r = reinterpret_cast<const ulonglong2*>(&sw[i * 8]);
            ulonglong2 q0 = r[0], q1 = r[1], q2 = r[2], q3 = r[3];
            u64 a = mul2(q3.x, uu);
            a = fma2(q0.x, db[0], a);
            a = fma2(q0.y, db[1], a);
            a = fma2(q1.x, db[2], a);
            a = fma2(q1.y, db[3], a);
            a = fma2(q2.x, db[4], a);
            a = fma2(q2.y, db[5], a);
            nd[i] = a;
        }
#pragma unroll
        for (int i = 0; i < 6; i++) db[i] = nd[i];

        // --- MLP: out = b2 + sum_j W2_j * tanh(W1_j . [db,x] + b1_j) ---
        u64 oacc = oinit;
#pragma unroll
        for (int j = 0; j < 20; j++) {
            const ulonglong2* r = reinterpret_cast<const ulonglong2*>(&sw[SW_ROWJ(j)]);
            ulonglong2 q0 = r[0], q1 = r[1], q2 = r[2], q3 = r[3], q4 = r[4], q5 = r[5], q6 = r[6];
            u64 acc = q6.x;  // b1_j
            acc = fma2(q0.x, db[0], acc);
            acc = fma2(q0.y, db[1], acc);
            acc = fma2(q1.x, db[2], acc);
            acc = fma2(q1.y, db[3], acc);
            acc = fma2(q2.x, db[4], acc);
            acc = fma2(q2.y, db[5], acc);
            acc = fma2(q3.x, xr[0], acc);
            acc = fma2(q3.y, xr[1], acc);
            acc = fma2(q4.x, xr[2], acc);
            acc = fma2(q4.y, xr[3], acc);
            acc = fma2(q5.x, xr[4], acc);
            acc = fma2(q5.y, xr[5], acc);
            float s0, s1;
            unpack2(acc, s0, s1);
            oacc = fma2(q6.y, pack2(tanh_(s0), tanh_(s1)), oacc);  // q6.y = W2_j
        }

        float o0, o1;
        unpack2(oacc, o0, o1);
        out[(size_t)t * BB + b0]  = o0;
        out[(size_t)t * BB + b1i] = o1;
    }
}

// ============================================================
extern "C" void kernel_launch(void* const* d_in, const int* in_sizes, int n_in,
                              void* d_out, int out_size) {
    (void)in_sizes; (void)n_in; (void)out_size;
    const float* inputs  = (const float*)d_in[0];
    const float* targets = (const float*)d_in[1];
    const float* Wx      = (const float*)d_in[2];
    const float* Wu      = (const float*)d_in[3];
    const float* W1      = (const float*)d_in[4];
    const float* b1      = (const float*)d_in[5];
    const float* W2      = (const float*)d_in[6];
    const float* b2      = (const float*)d_in[7];
    float* out = (float*)d_out;

    kP<<<1, 64>>>(Wx, Wu);
    dim3 gA(BB / 256, NCH);
    kA<<<gA, 256>>>(targets);
    kB<<<BB / 256, 256>>>();
    dim3 gC(HB / 128, NCH);
    kC<<<gC, 128>>>(inputs, targets, Wx, Wu, W1, b1, W2, b2, out);
}

// round 3
// speedup vs baseline: 1.3029x; 1.1615x over previous
#include <cuda_runtime.h>

// Problem constants (fixed by the reference).
#define TT   1024
#define BB   16384
#define CH   64          // steps per chunk
#define NCH  (TT / CH)   // 16 chunks
#define HB   (BB / 2)    // batch pairs
#define SS   4           // steps tiled together in kC

typedef unsigned long long u64;

static_assert(CH == 64, "power-table size assumes CH=64");
static_assert(TT % CH == 0, "");
static_assert(CH % SS == 0, "");

// Scratch.
__device__ float g_part[NCH * 6 * BB];   // zero-state per-chunk db partials, [chunk][dim][batch]
__device__ float g_ckpt[NCH * 6 * BB];   // true db at chunk entry
__device__ float g_m[CH * 6];            // m_s = Wx^s * Wu
__device__ float g_M64[36];              // Wx^64

// ---- f32x2 helpers (sm_100+ packed fp32 pipe) ----
__device__ __forceinline__ u64 pack2(float lo, float hi) {
    u64 r; asm("mov.b64 %0,{%1,%2};" : "=l"(r) : "f"(lo), "f"(hi)); return r;
}
__device__ __forceinline__ void unpack2(u64 v, float& lo, float& hi) {
    asm("mov.b64 {%0,%1},%2;" : "=f"(lo), "=f"(hi) : "l"(v));
}
__device__ __forceinline__ u64 fma2(u64 a, u64 b, u64 c) {
    u64 d; asm("fma.rn.f32x2 %0,%1,%2,%3;" : "=l"(d) : "l"(a), "l"(b), "l"(c)); return d;
}
__device__ __forceinline__ u64 mul2(u64 a, u64 b) {
    u64 d; asm("mul.rn.f32x2 %0,%1,%2;" : "=l"(d) : "l"(a), "l"(b)); return d;
}
__device__ __forceinline__ float tanh_(float x) {
    float y; asm("tanh.approx.f32 %0,%1;" : "=f"(y) : "f"(x)); return y;
}

// ============================================================
// Kernel P: tiny precompute. m_s = Wx^s Wu (s=0..63) and Wx^64.
// ============================================================
__global__ void __launch_bounds__(64) kP(const float* __restrict__ Wx,
                                         const float* __restrict__ Wu) {
    __shared__ float sM[36], sm[6], sP[36], st[36];
    int t = threadIdx.x;
    if (t < 36) sM[t] = Wx[t];
    if (t < 6)  sm[t] = Wu[t];
    __syncthreads();

    for (int s = 0; s < CH; s++) {
        if (t < 6) g_m[s * 6 + t] = sm[t];
        __syncthreads();
        float nv = 0.f;
        if (t < 6) {
#pragma unroll
            for (int k = 0; k < 6; k++) nv = fmaf(sM[t * 6 + k], sm[k], nv);
        }
        __syncthreads();
        if (t < 6) sm[t] = nv;
        __syncthreads();
    }

    if (t < 36) sP[t] = sM[t];
    __syncthreads();
    for (int p = 0; p < 6; p++) {
        if (t < 36) {
            int i = t / 6, j = t % 6;
            float a = 0.f;
#pragma unroll
            for (int k = 0; k < 6; k++) a = fmaf(sP[i * 6 + k], sP[k * 6 + j], a);
            st[t] = a;
        }
        __syncthreads();
        if (t < 36) sP[t] = st[t];
        __syncthreads();
    }
    if (t < 36) g_M64[t] = sP[t];
}

// ============================================================
// Kernel A: per-chunk zero-state db partials via convolution.
// ============================================================
__global__ void __launch_bounds__(256) kA(const float* __restrict__ targets) {
    __shared__ float sm[CH * 6];
    int tid = threadIdx.x;
    for (int i = tid; i < CH * 6; i += 256) sm[i] = g_m[i];
    __syncthreads();

    int b = blockIdx.x * 256 + tid;
    int c = blockIdx.y;
    int t0 = c * CH;

    float acc[6] = {0.f, 0.f, 0.f, 0.f, 0.f, 0.f};
#pragma unroll 8
    for (int s = 0; s < CH; s++) {
        int t = t0 + s;
        float u = 0.f;
        if (t > 0) u = targets[(size_t)(t - 1) * BB + b];
        const float* mm = &sm[(CH - 1 - s) * 6];
#pragma unroll
        for (int i = 0; i < 6; i++) acc[i] = fmaf(mm[i], u, acc[i]);
    }
#pragma unroll
    for (int i = 0; i < 6; i++)
        g_part[((size_t)c * 6 + i) * BB + b] = acc[i];
}

// ============================================================
// Kernel B: scan across chunks: db_in(c+1) = Wx^64 * db_in(c) + partial(c).
// ============================================================
__global__ void __launch_bounds__(256) kB() {
    __shared__ float sM[36];
    int tid = threadIdx.x;
    if (tid < 36) sM[tid] = g_M64[tid];
    __syncthreads();

    int b = blockIdx.x * 256 + tid;
    float v[6] = {0.f, 0.f, 0.f, 0.f, 0.f, 0.f};
#pragma unroll 1
    for (int c = 0; c < NCH; c++) {
#pragma unroll
        for (int i = 0; i < 6; i++)
            g_ckpt[((size_t)c * 6 + i) * BB + b] = v[i];
        float pr[6];
#pragma unroll
        for (int i = 0; i < 6; i++)
            pr[i] = g_part[((size_t)c * 6 + i) * BB + b];
        float nv[6];
#pragma unroll
        for (int i = 0; i < 6; i++) {
            float a = pr[i];
#pragma unroll
            for (int j = 0; j < 6; j++) a = fmaf(sM[i * 6 + j], v[j], a);
            nv[i] = a;
        }
#pragma unroll
        for (int i = 0; i < 6; i++) v[i] = nv[i];
    }
}

// ============================================================
// Kernel C: fused MLP, step-tiled by SS=4.
// One thread = one pair of batch elements (b, b+HB) in f32x2 lanes,
// one chunk of 64 steps, processed in groups of 4 steps:
//   phase 1: advance db 4 steps, stash packed ni=[db,x] per step (48 u64 regs)
//   phase 2: sweep 20 hidden rows once, 4 independent fma2 chains per row.
// SMEM (u64 units):
//   rows i=0..5 at i*8:       [Wx i0..i5, Wu i, pad]
//   rows j=0..19 at 48+j*16:  [W1 j0..j11, b1 j, W2 j, pad, pad]
// ============================================================
#define SW_ROWJ(j) (48 + (j) * 16)
__global__ void __launch_bounds__(128, 3) kC(const float* __restrict__ inputs,
                                             const float* __restrict__ targets,
                                             const float* __restrict__ Wx,
                                             const float* __restrict__ Wu,
                                             const float* __restrict__ W1,
                                             const float* __restrict__ b1,
                                             const float* __restrict__ W2,
                                             const float* __restrict__ b2,
                                             float* __restrict__ out) {
    __shared__ __align__(16) u64 sw[368];
    int tid = threadIdx.x;

    if (tid < 36) {
        float w = __ldg(Wx + tid);
        sw[(tid / 6) * 8 + (tid % 6)] = pack2(w, w);
    } else if (tid < 42) {
        int i = tid - 36;
        float w = __ldg(Wu + i);
        sw[i * 8 + 6] = pack2(w, w);
        sw[i * 8 + 7] = 0ull;
    } else if (tid < 62) {
        int j = tid - 42;
        for (int i = 0; i < 12; i++) {
            float w = __ldg(W1 + j * 12 + i);
            sw[SW_ROWJ(j) + i] = pack2(w, w);
        }
        float bj = __ldg(b1 + j);
        sw[SW_ROWJ(j) + 12] = pack2(bj, bj);
        float w2j = __ldg(W2 + j);
        sw[SW_ROWJ(j) + 13] = pack2(w2j, w2j);
        sw[SW_ROWJ(j) + 14] = 0ull;
        sw[SW_ROWJ(j) + 15] = 0ull;
    }
    __syncthreads();

    const int c   = blockIdx.y;
    const int p   = blockIdx.x * 128 + tid;   // 0..HB-1
    const int b0  = p;
    const int b1i = p + HB;

    u64 db[6];
#pragma unroll
    for (int i = 0; i < 6; i++)
        db[i] = pack2(g_ckpt[((size_t)c * 6 + i) * BB + b0],
                      g_ckpt[((size_t)c * 6 + i) * BB + b1i]);

    float b2v = __ldg(b2);
    const u64 oinit = pack2(b2v, b2v);

    const float2* xin = reinterpret_cast<const float2*>(inputs);
    // running offsets (float2 units for x, float units for targets/out)
    size_t xo0 = ((size_t)c * CH * BB + b0)  * 3;
    size_t xo1 = ((size_t)c * CH * BB + b1i) * 3;
    size_t to  = (size_t)c * CH * BB;        // out offset of step t (add b)

#pragma unroll 1
    for (int sg = 0; sg < CH; sg += SS) {
        u64 ni[SS][12];

        // ---- phase 1: db recurrence for SS steps, gather ni ----
#pragma unroll
        for (int s = 0; s < SS; s++) {
            int t = c * CH + sg + s;

            float2 xa0 = xin[xo0], xb0 = xin[xo0 + 1], xc0 = xin[xo0 + 2];
            float2 xa1 = xin[xo1], xb1 = xin[xo1 + 1], xc1 = xin[xo1 + 2];
            xo0 += (size_t)BB * 3;
            xo1 += (size_t)BB * 3;

            float u0 = 0.f, u1v = 0.f;
            if (t > 0) {
                size_t tb = (size_t)(t - 1) * BB;
                u0  = targets[tb + b0];
                u1v = targets[tb + b1i];
            }
            u64 uu = pack2(u0, u1v);

            u64 nd[6];
#pragma unroll
            for (int i = 0; i < 6; i++) {
                const ulonglong2* r = reinterpret_cast<const ulonglong2*>(&sw[i * 8]);
                ulonglong2 q0 = r[0], q1 = r[1], q2 = r[2], q3 = r[3];
                u64 a = mul2(q3.x, uu);
                a = fma2(q0.x, db[0], a);
                a = fma2(q0.y, db[1], a);
                a = fma2(q1.x, db[2], a);
                a = fma2(q1.y, db[3], a);
                a = fma2(q2.x, db[4], a);
                a = fma2(q2.y, db[5], a);
                nd[i] = a;
            }
#pragma unroll
            for (int i = 0; i < 6; i++) { db[i] = nd[i]; ni[s][i] = nd[i]; }
            ni[s][6]  = pack2(xa0.x, xa1.x);
            ni[s][7]  = pack2(xa0.y, xa1.y);
            ni[s][8]  = pack2(xb0.x, xb1.x);
            ni[s][9]  = pack2(xb0.y, xb1.y);
            ni[s][10] = pack2(xc0.x, xc1.x);
            ni[s][11] = pack2(xc0.y, xc1.y);
        }

        // ---- phase 2: 20 hidden rows over SS steps ----
        u64 oacc[SS];
#pragma unroll
        for (int s = 0; s < SS; s++) oacc[s] = oinit;

#pragma unroll
        for (int j = 0; j < 20; j++) {
            const ulonglong2* r = reinterpret_cast<const ulonglong2*>(&sw[SW_ROWJ(j)]);
            ulonglong2 q0 = r[0], q1 = r[1], q2 = r[2], q3 = r[3], q4 = r[4], q5 = r[5], q6 = r[6];
            u64 acc[SS];
#pragma unroll
            for (int s = 0; s < SS; s++) acc[s] = q6.x;  // b1_j
#pragma unroll
            for (int s = 0; s < SS; s++) {
                acc[s] = fma2(q0.x, ni[s][0], acc[s]);
                acc[s] = fma2(q0.y, ni[s][1], acc[s]);
                acc[s] = fma2(q1.x, ni[s][2], acc[s]);
                acc[s] = fma2(q1.y, ni[s][3], acc[s]);
                acc[s] = fma2(q2.x, ni[s][4], acc[s]);
                acc[s] = fma2(q2.y, ni[s][5], acc[s]);
                acc[s] = fma2(q3.x, ni[s][6], acc[s]);
                acc[s] = fma2(q3.y, ni[s][7], acc[s]);
                acc[s] = fma2(q4.x, ni[s][8], acc[s]);
                acc[s] = fma2(q4.y, ni[s][9], acc[s]);
                acc[s] = fma2(q5.x, ni[s][10], acc[s]);
                acc[s] = fma2(q5.y, ni[s][11], acc[s]);
            }
#pragma unroll
            for (int s = 0; s < SS; s++) {
                float s0, s1;
                unpack2(acc[s], s0, s1);
                oacc[s] = fma2(q6.y, pack2(tanh_(s0), tanh_(s1)), oacc[s]);  // q6.y = W2_j
            }
        }

        // ---- stores ----
#pragma unroll
        for (int s = 0; s < SS; s++) {
            float o0, o1;
            unpack2(oacc[s], o0, o1);
            size_t ob = to + (size_t)(sg + s) * BB;
            out[ob + b0]  = o0;
            out[ob + b1i] = o1;
        }
    }
}

// ============================================================
extern "C" void kernel_launch(void* const* d_in, const int* in_sizes, int n_in,
                              void* d_out, int out_size) {
    (void)in_sizes; (void)n_in; (void)out_size;
    const float* inputs  = (const float*)d_in[0];
    const float* targets = (const float*)d_in[1];
    const float* Wx      = (const float*)d_in[2];
    const float* Wu      = (const float*)d_in[3];
    const float* W1      = (const float*)d_in[4];
    const float* b1      = (const float*)d_in[5];
    const float* W2      = (const float*)d_in[6];
    const float* b2      = (const float*)d_in[7];
    float* out = (float*)d_out;

    kP<<<1, 64>>>(Wx, Wu);
    dim3 gA(BB / 256, NCH);
    kA<<<gA, 256>>>(targets);
    kB<<<BB / 256, 256>>>();
    dim3 gC(HB / 128, NCH);
    kC<<<gC, 128>>>(inputs, targets, Wx, Wu, W1, b1, W2, b2, out);
}

// round 4
// speedup vs baseline: 2.2220x; 1.7054x over previous
#include <cuda_runtime.h>

// Problem constants (fixed by the reference).
#define TT   1024
#define BB   16384
#define CH   64          // steps per chunk
#define NCH  (TT / CH)   // 16 chunks
#define HB   (BB / 2)    // batch pairs
#define SS   4           // steps tiled together in kC

typedef unsigned long long u64;

static_assert(CH == 64, "power-table size assumes CH=64");
static_assert(TT % CH == 0, "");
static_assert(CH % SS == 0, "");

// Scratch.
__device__ float g_part[NCH * 6 * BB];   // zero-state per-chunk db partials
__device__ float g_ckpt[NCH * 6 * BB];   // true db at chunk entry
__device__ float g_m[CH * 6];            // m_s = Wx^s * Wu
__device__ float g_M64[36];              // Wx^64

// Duplicated-pair weight table, staged by kP then copied to constant bank.
// Layout (u64 units):
//   rows i=0..5 at i*8: [Wx i0..i5 (pairs), Wu i (pair), pad]   (cw[7] = b2 pair)
//   rows j=0..19 at 48+j*16: [W1 j0..j11 (pairs), b1 j, W2 j, pad, pad]
#define CW_N 368
#define SW_ROWJ(j) (48 + (j) * 16)
__device__ u64 g_wdup[CW_N];
__constant__ __align__(16) u64 cw[CW_N];

// ---- f32x2 helpers (sm_100+ packed fp32 pipe) ----
__device__ __forceinline__ u64 pack2(float lo, float hi) {
    u64 r; asm("mov.b64 %0,{%1,%2};" : "=l"(r) : "f"(lo), "f"(hi)); return r;
}
__device__ __forceinline__ void unpack2(u64 v, float& lo, float& hi) {
    asm("mov.b64 {%0,%1},%2;" : "=f"(lo), "=f"(hi) : "l"(v));
}
__device__ __forceinline__ u64 fma2(u64 a, u64 b, u64 c) {
    u64 d; asm("fma.rn.f32x2 %0,%1,%2,%3;" : "=l"(d) : "l"(a), "l"(b), "l"(c)); return d;
}
__device__ __forceinline__ u64 mul2(u64 a, u64 b) {
    u64 d; asm("mul.rn.f32x2 %0,%1,%2;" : "=l"(d) : "l"(a), "l"(b)); return d;
}
__device__ __forceinline__ float tanh_(float x) {
    float y; asm("tanh.approx.f32 %0,%1;" : "=f"(y) : "f"(x)); return y;
}

// ============================================================
// Kernel P: precompute m_s = Wx^s Wu, Wx^64, and the duplicated
// weight-pair table g_wdup. One block of 64 threads.
// ============================================================
__global__ void __launch_bounds__(64) kP(const float* __restrict__ Wx,
                                         const float* __restrict__ Wu,
                                         const float* __restrict__ W1,
                                         const float* __restrict__ b1,
                                         const float* __restrict__ W2,
                                         const float* __restrict__ b2) {
    __shared__ float sM[36], sm[6], sP[36], st[36];
    int t = threadIdx.x;
    if (t < 36) sM[t] = Wx[t];
    if (t < 6)  sm[t] = Wu[t];
    __syncthreads();

    for (int s = 0; s < CH; s++) {
        if (t < 6) g_m[s * 6 + t] = sm[t];
        __syncthreads();
        float nv = 0.f;
        if (t < 6) {
#pragma unroll
            for (int k = 0; k < 6; k++) nv = fmaf(sM[t * 6 + k], sm[k], nv);
        }
        __syncthreads();
        if (t < 6) sm[t] = nv;
        __syncthreads();
    }

    if (t < 36) sP[t] = sM[t];
    __syncthreads();
    for (int p = 0; p < 6; p++) {
        if (t < 36) {
            int i = t / 6, j = t % 6;
            float a = 0.f;
#pragma unroll
            for (int k = 0; k < 6; k++) a = fmaf(sP[i * 6 + k], sP[k * 6 + j], a);
            st[t] = a;
        }
        __syncthreads();
        if (t < 36) sP[t] = st[t];
        __syncthreads();
    }
    if (t < 36) g_M64[t] = sP[t];

    // ---- duplicated-pair weight table ----
    if (t < 36) {
        float w = Wx[t];
        g_wdup[(t / 6) * 8 + (t % 6)] = pack2(w, w);
    } else if (t < 42) {
        int i = t - 36;
        float w = Wu[i];
        g_wdup[i * 8 + 6] = pack2(w, w);
        if (i > 0) g_wdup[i * 8 + 7] = 0ull;
    } else if (t < 62) {
        int j = t - 42;
        for (int i = 0; i < 12; i++) {
            float w = W1[j * 12 + i];
            g_wdup[SW_ROWJ(j) + i] = pack2(w, w);
        }
        float bj = b1[j];
        g_wdup[SW_ROWJ(j) + 12] = pack2(bj, bj);
        float w2j = W2[j];
        g_wdup[SW_ROWJ(j) + 13] = pack2(w2j, w2j);
        g_wdup[SW_ROWJ(j) + 14] = 0ull;
        g_wdup[SW_ROWJ(j) + 15] = 0ull;
    } else if (t == 62) {
        float bv = b2[0];
        g_wdup[7] = pack2(bv, bv);   // b2 pair in row-0 pad slot
    }
}

// ============================================================
// Kernel A: per-chunk zero-state db partials via convolution.
// ============================================================
__global__ void __launch_bounds__(256) kA(const float* __restrict__ targets) {
    __shared__ float sm[CH * 6];
    int tid = threadIdx.x;
    for (int i = tid; i < CH * 6; i += 256) sm[i] = g_m[i];
    __syncthreads();

    int b = blockIdx.x * 256 + tid;
    int c = blockIdx.y;
    int t0 = c * CH;

    float acc[6] = {0.f, 0.f, 0.f, 0.f, 0.f, 0.f};
#pragma unroll 8
    for (int s = 0; s < CH; s++) {
        int t = t0 + s;
        float u = 0.f;
        if (t > 0) u = targets[(size_t)(t - 1) * BB + b];
        const float* mm = &sm[(CH - 1 - s) * 6];
#pragma unroll
        for (int i = 0; i < 6; i++) acc[i] = fmaf(mm[i], u, acc[i]);
    }
#pragma unroll
    for (int i = 0; i < 6; i++)
        g_part[((size_t)c * 6 + i) * BB + b] = acc[i];
}

// ============================================================
// Kernel B: scan across chunks: db_in(c+1) = Wx^64 * db_in(c) + partial(c).
// ============================================================
__global__ void __launch_bounds__(256) kB() {
    __shared__ float sM[36];
    int tid = threadIdx.x;
    if (tid < 36) sM[tid] = g_M64[tid];
    __syncthreads();

    int b = blockIdx.x * 256 + tid;
    float v[6] = {0.f, 0.f, 0.f, 0.f, 0.f, 0.f};
#pragma unroll 1
    for (int c = 0; c < NCH; c++) {
#pragma unroll
        for (int i = 0; i < 6; i++)
            g_ckpt[((size_t)c * 6 + i) * BB + b] = v[i];
        float pr[6];
#pragma unroll
        for (int i = 0; i < 6; i++)
            pr[i] = g_part[((size_t)c * 6 + i) * BB + b];
        float nv[6];
#pragma unroll
        for (int i = 0; i < 6; i++) {
            float a = pr[i];
#pragma unroll
            for (int j = 0; j < 6; j++) a = fmaf(sM[i * 6 + j], v[j], a);
            nv[i] = a;
        }
#pragma unroll
        for (int i = 0; i < 6; i++) v[i] = nv[i];
    }
}

// ============================================================
// Kernel C: fused MLP, step-tiled by SS=4, weights from the constant bank
// (warp-uniform LDCU -> UR operands, no SMEM, no weight LDS).
// One thread = pair (b, b+HB) in f32x2 lanes, one chunk of 64 steps.
// ============================================================
__global__ void __launch_bounds__(128, 3) kC(const float* __restrict__ inputs,
                                             const float* __restrict__ targets,
                                             float* __restrict__ out) {
    const int tid = threadIdx.x;
    const int c   = blockIdx.y;
    const int p   = blockIdx.x * 128 + tid;   // 0..HB-1
    const int b0  = p;
    const int b1i = p + HB;

    u64 db[6];
#pragma unroll
    for (int i = 0; i < 6; i++)
        db[i] = pack2(g_ckpt[((size_t)c * 6 + i) * BB + b0],
                      g_ckpt[((size_t)c * 6 + i) * BB + b1i]);

    // incremental byte pointers
    const char* xp0 = (const char*)inputs + ((size_t)c * CH * BB + b0)  * 24;
    const char* xp1 = (const char*)inputs + ((size_t)c * CH * BB + b1i) * 24;
    const char* tp0 = (const char*)targets + ((size_t)(c * CH - 1) * BB + b0)  * 4;
    const char* tp1 = (const char*)targets + ((size_t)(c * CH - 1) * BB + b1i) * 4;
    char* op0 = (char*)out + ((size_t)c * CH * BB + b0)  * 4;
    char* op1 = (char*)out + ((size_t)c * CH * BB + b1i) * 4;

    float b2lo, b2hi;
    unpack2(cw[7], b2lo, b2hi);

#pragma unroll 1
    for (int sg = 0; sg < CH; sg += SS) {
        u64 ni[SS][12];

        // ---- phase 1: db recurrence for SS steps, gather ni ----
#pragma unroll
        for (int s = 0; s < SS; s++) {
            float2 xa0 = ((const float2*)xp0)[0];
            float2 xb0 = ((const float2*)xp0)[1];
            float2 xc0 = ((const float2*)xp0)[2];
            float2 xa1 = ((const float2*)xp1)[0];
            float2 xb1 = ((const float2*)xp1)[1];
            float2 xc1 = ((const float2*)xp1)[2];
            xp0 += (size_t)BB * 24;
            xp1 += (size_t)BB * 24;

            float u0 = 0.f, u1v = 0.f;
            if (c + sg + s > 0) {                 // t > 0
                u0  = *(const float*)tp0;
                u1v = *(const float*)tp1;
            }
            tp0 += (size_t)BB * 4;
            tp1 += (size_t)BB * 4;
            u64 uu = pack2(u0, u1v);

            u64 nd[6];
#pragma unroll
            for (int i = 0; i < 6; i++) {
                const u64* r = &cw[i * 8];
                u64 a = mul2(r[6], uu);
                a = fma2(r[0], db[0], a);
                a = fma2(r[1], db[1], a);
                a = fma2(r[2], db[2], a);
                a = fma2(r[3], db[3], a);
                a = fma2(r[4], db[4], a);
                a = fma2(r[5], db[5], a);
                nd[i] = a;
            }
#pragma unroll
            for (int i = 0; i < 6; i++) { db[i] = nd[i]; ni[s][i] = nd[i]; }
            ni[s][6]  = pack2(xa0.x, xa1.x);
            ni[s][7]  = pack2(xa0.y, xa1.y);
            ni[s][8]  = pack2(xb0.x, xb1.x);
            ni[s][9]  = pack2(xb0.y, xb1.y);
            ni[s][10] = pack2(xc0.x, xc1.x);
            ni[s][11] = pack2(xc0.y, xc1.y);
        }

        // ---- phase 2: 20 hidden rows over SS steps ----
        float o0[SS], o1[SS];
#pragma unroll
        for (int s = 0; s < SS; s++) { o0[s] = b2lo; o1[s] = b2hi; }

#pragma unroll
        for (int j = 0; j < 20; j++) {
            const u64* r = &cw[SW_ROWJ(j)];
            u64 bb1 = r[12];
            u64 acc[SS];
#pragma unroll
            for (int s = 0; s < SS; s++) acc[s] = bb1;
#pragma unroll
            for (int s = 0; s < SS; s++) {
                acc[s] = fma2(r[0],  ni[s][0],  acc[s]);
                acc[s] = fma2(r[1],  ni[s][1],  acc[s]);
                acc[s] = fma2(r[2],  ni[s][2],  acc[s]);
                acc[s] = fma2(r[3],  ni[s][3],  acc[s]);
                acc[s] = fma2(r[4],  ni[s][4],  acc[s]);
                acc[s] = fma2(r[5],  ni[s][5],  acc[s]);
                acc[s] = fma2(r[6],  ni[s][6],  acc[s]);
                acc[s] = fma2(r[7],  ni[s][7],  acc[s]);
                acc[s] = fma2(r[8],  ni[s][8],  acc[s]);
                acc[s] = fma2(r[9],  ni[s][9],  acc[s]);
                acc[s] = fma2(r[10], ni[s][10], acc[s]);
                acc[s] = fma2(r[11], ni[s][11], acc[s]);
            }
            float w2lo, w2hi;
            unpack2(r[13], w2lo, w2hi);
#pragma unroll
            for (int s = 0; s < SS; s++) {
                float a0, a1;
                unpack2(acc[s], a0, a1);
                o0[s] = fmaf(w2lo, tanh_(a0), o0[s]);
                o1[s] = fmaf(w2hi, tanh_(a1), o1[s]);
            }
        }

        // ---- stores ----
#pragma unroll
        for (int s = 0; s < SS; s++) {
            *(float*)(op0) = o0[s];
            *(float*)(op1) = o1[s];
            op0 += (size_t)BB * 4;
            op1 += (size_t)BB * 4;
        }
    }
}

// ============================================================
extern "C" void kernel_launch(void* const* d_in, const int* in_sizes, int n_in,
                              void* d_out, int out_size) {
    (void)in_sizes; (void)n_in; (void)out_size;
    const float* inputs  = (const float*)d_in[0];
    const float* targets = (const float*)d_in[1];
    const float* Wx      = (const float*)d_in[2];
    const float* Wu      = (const float*)d_in[3];
    const float* W1      = (const float*)d_in[4];
    const float* b1      = (const float*)d_in[5];
    const float* W2      = (const float*)d_in[6];
    const float* b2      = (const float*)d_in[7];
    float* out = (float*)d_out;

    kP<<<1, 64>>>(Wx, Wu, W1, b1, W2, b2);

    // Stage the duplicated weight table into the constant bank (D2D memcpy node).
    void* wd = nullptr;
    cudaGetSymbolAddress(&wd, g_wdup);
    cudaMemcpyToSymbolAsync(cw, wd, CW_N * sizeof(u64), 0,
                            cudaMemcpyDeviceToDevice, 0);

    dim3 gA(BB / 256, NCH);
    kA<<<gA, 256>>>(targets);
    kB<<<BB / 256, 256>>>();
    dim3 gC(HB / 128, NCH);
    kC<<<gC, 128>>>(inputs, targets, out);
}